// round 14
// baseline (speedup 1.0000x reference)
#include <cuda_runtime.h>
#include <cuda_bf16.h>
#include <cuda_fp16.h>
#include <math.h>
#include <stdint.h>

#define HID   246
#define NMAX  50000
#define EMAX  320000
#define KP    256            // padded K (activation row stride, halves)
#define HSP   256            // padded g_hs row stride (halves)
#define NBLK  ((NMAX + 255) / 256)

// ---------------- device-global scratch (no allocation allowed) ------------
__device__ __align__(16) float g_dinv[NMAX];
__device__ __align__(16) __half g_hs[NMAX * HSP];     // GEMM out, fp16
__device__ __align__(16) __half g_a [NMAX * KP];      // activations, fp16
__device__ __align__(16) __half g_w [4 * KP * KP];    // W [k][n] padded, fp16
__device__ __align__(16) float g_bpad[4 * HSP];       // padded biases
__device__ int g_src[EMAX];
__device__ int g_dst[EMAX];
__device__ int g_cnt[NMAX];
__device__ int g_rsI[NMAX];
__device__ int g_rowstart[NMAX];
__device__ int g_cursor[NMAX];
__device__ int g_csr[EMAX];
__device__ int g_bsum[NBLK];
__device__ int g_boff[NBLK];
__device__ int g_is64;

// ---------------- helpers ---------------------------------------------------
__device__ __forceinline__ unsigned smaddr(const void* p) {
    return (unsigned)__cvta_generic_to_shared(p);
}
__device__ __forceinline__ void ldsm_x4(unsigned a, unsigned& r0, unsigned& r1,
                                        unsigned& r2, unsigned& r3) {
    asm volatile("ldmatrix.sync.aligned.m8n8.x4.shared.b16 {%0,%1,%2,%3}, [%4];"
                 : "=r"(r0), "=r"(r1), "=r"(r2), "=r"(r3) : "r"(a));
}
__device__ __forceinline__ void ldsm_x4_t(unsigned a, unsigned& r0, unsigned& r1,
                                          unsigned& r2, unsigned& r3) {
    asm volatile("ldmatrix.sync.aligned.m8n8.x4.trans.shared.b16 {%0,%1,%2,%3}, [%4];"
                 : "=r"(r0), "=r"(r1), "=r"(r2), "=r"(r3) : "r"(a));
}
__device__ __forceinline__ void mma_f16(float* c, const unsigned* a, unsigned b0, unsigned b1) {
    asm volatile("mma.sync.aligned.m16n8k16.row.col.f32.f16.f16.f32 "
                 "{%0,%1,%2,%3}, {%4,%5,%6,%7}, {%8,%9}, {%0,%1,%2,%3};"
                 : "+f"(c[0]), "+f"(c[1]), "+f"(c[2]), "+f"(c[3])
                 : "r"(a[0]), "r"(a[1]), "r"(a[2]), "r"(a[3]), "r"(b0), "r"(b1));
}
__device__ __forceinline__ void cpa16(unsigned dst, const void* src) {
    asm volatile("cp.async.cg.shared.global [%0], [%1], 16;" :: "r"(dst), "l"(src));
}
__device__ __forceinline__ void cpa16z(unsigned dst, const void* src, int srcbytes) {
    asm volatile("cp.async.cg.shared.global [%0], [%1], 16, %2;"
                 :: "r"(dst), "l"(src), "r"(srcbytes));
}
#define CPA_COMMIT() asm volatile("cp.async.commit_group;" ::: "memory")
#define CPA_WAIT(n)  asm volatile("cp.async.wait_group %0;" :: "n"(n) : "memory")

// ---------------- conversions ----------------------------------------------
__global__ void conv_x_k(const float* __restrict__ x, int total4) {
    int i = blockIdx.x * blockDim.x + threadIdx.x;
    if (i >= total4) return;
    float4 v = ((const float4*)x)[i];
    __half2 h01 = __floats2half2_rn(v.x, v.y);
    __half2 h23 = __floats2half2_rn(v.z, v.w);
    uint2 u;
    u.x = *(unsigned*)&h01;
    u.y = *(unsigned*)&h23;
    ((uint2*)g_a)[i] = u;
}
// last block also pads the biases (saves a launch)
__global__ void conv_w4_k(const float* __restrict__ W1, const float* __restrict__ W2,
                          const float* __restrict__ W3, const float* __restrict__ W4,
                          const float* __restrict__ b1, const float* __restrict__ b2,
                          const float* __restrict__ b3, const float* __restrict__ b4,
                          int K1, int nblk) {
    if (blockIdx.x == nblk - 1) {
        int c = threadIdx.x;
        const float* bs[4] = {b1, b2, b3, b4};
        #pragma unroll
        for (int l = 0; l < 4; l++)
            g_bpad[l * HSP + c] = (c < HID) ? bs[l][c] : 0.0f;
    }
    int i = blockIdx.x * blockDim.x + threadIdx.x;
    if (i >= 4 * KP * KP) return;
    int layer = i >> 16;
    int j = i & 0xFFFF;
    int r = j >> 8, c = j & 255;
    const float* W = (layer == 0) ? W1 : (layer == 1) ? W2 : (layer == 2) ? W3 : W4;
    int K = (layer == 0) ? K1 : HID;
    float v = (r < K && c < HID) ? W[r * HID + c] : 0.0f;
    g_w[i] = __float2half(v);
}

// ---------------- edge preprocessing ---------------------------------------
__global__ void detect_zero_k(const int* __restrict__ w, int nwords, int N) {
    int i = blockIdx.x * blockDim.x + threadIdx.x;
    if (i < N) g_cnt[i] = 0;
    if (blockIdx.x == 0) {
        __shared__ int any;
        if (threadIdx.x == 0) any = 0;
        __syncthreads();
        for (int j = 2 * threadIdx.x + 1; j < nwords; j += 2 * blockDim.x)
            if (w[j] != 0) any = 1;
        __syncthreads();
        if (threadIdx.x == 0) g_is64 = (any == 0) ? 1 : 0;
    }
}
__global__ void convert_count_k(const int* __restrict__ w, int E) {
    int i = blockIdx.x * blockDim.x + threadIdx.x;
    if (i >= E) return;
    int s, d;
    if (g_is64) { s = w[2 * i]; d = w[2 * (E + i)]; }
    else        { s = w[i];     d = w[E + i]; }
    g_src[i] = s;
    g_dst[i] = d;
    atomicAdd(&g_cnt[d], 1);
}
__global__ void scan1_k(int N) {
    __shared__ int sh[256];
    int i = blockIdx.x * 256 + threadIdx.x;
    int v = (i < N) ? g_cnt[i] : 0;
    sh[threadIdx.x] = v;
    __syncthreads();
    for (int o = 1; o < 256; o <<= 1) {
        int t = (threadIdx.x >= o) ? sh[threadIdx.x - o] : 0;
        __syncthreads();
        sh[threadIdx.x] += t;
        __syncthreads();
    }
    if (i < N) g_rsI[i] = sh[threadIdx.x];
    if (threadIdx.x == 255) g_bsum[blockIdx.x] = sh[255];
}
__global__ void scan2_k(int NB) {
    __shared__ int sh[256];
    int v = (threadIdx.x < NB) ? g_bsum[threadIdx.x] : 0;
    sh[threadIdx.x] = v;
    __syncthreads();
    for (int o = 1; o < 256; o <<= 1) {
        int t = (threadIdx.x >= o) ? sh[threadIdx.x - o] : 0;
        __syncthreads();
        sh[threadIdx.x] += t;
        __syncthreads();
    }
    if (threadIdx.x < NB) g_boff[threadIdx.x] = sh[threadIdx.x] - v;
}
__global__ void scan3_dinv_k(int N) {
    int i = blockIdx.x * blockDim.x + threadIdx.x;
    if (i >= N) return;
    int cnt = g_cnt[i];
    int ex = g_rsI[i] - cnt + g_boff[i >> 8];
    g_rowstart[i] = ex;
    g_cursor[i]   = ex;
    g_dinv[i]     = rsqrtf((float)(cnt + 1));
}
__global__ void fill_csr_k(int E) {
    int e = blockIdx.x * blockDim.x + threadIdx.x;
    if (e >= E) return;
    int d = g_dst[e];
    int pos = atomicAdd(&g_cursor[d], 1);
    g_csr[pos] = g_src[e];
}

// ---------------- fp16 tensor-core GEMM (occ-3, 2-stage, K-chunk 64) -------
// Tile 64x128, 8 warps (2 M x 4 N), warp tile 32x32, 3 CTAs/SM.
#define BM 64
#define BN 128
#define BKB 64
#define NCHUNK 4
#define NSTAGE 2
#define A_STRIDE 72
#define B_STRIDE 136
#define A_ST_BYTES (BM * A_STRIDE * 2)                  // 9216
#define B_ST_BYTES (BKB * B_STRIDE * 2)                 // 17408
#define GEMM_SMEM (NSTAGE * (A_ST_BYTES + B_ST_BYTES))  // 53248

__global__ __launch_bounds__(256, 3) void gemm_tc_k(int Mstart, int Mend,
                                                    int layer, int scale) {
    extern __shared__ char dsm[];
    __half (*As)[BM][A_STRIDE] = (__half (*)[BM][A_STRIDE])dsm;
    __half (*Bs)[BKB][B_STRIDE] = (__half (*)[BKB][B_STRIDE])(dsm + NSTAGE * A_ST_BYTES);
    const int tid  = threadIdx.x;
    const int lane = tid & 31;
    const int wid  = tid >> 5;
    const int wm   = (wid & 1) * 32;        // 2 M warps x 4 N warps
    const int wn   = (wid >> 1) * 32;
    const int row0 = Mstart + blockIdx.y * BM;
    const int col0 = blockIdx.x * BN;
    const __half* wbase = g_w + (size_t)layer * KP * KP;

    float acc[2][4][4];
    #pragma unroll
    for (int a = 0; a < 2; a++)
        #pragma unroll
        for (int b = 0; b < 4; b++)
            #pragma unroll
            for (int c = 0; c < 4; c++) acc[a][b][c] = 0.0f;

    // A tile: 64 rows x 64 halves = 512 uint4 (2/thread)
    // B tile: 64 rows x 128 halves = 1024 uint4 (4/thread)
    auto issue = [&](int chunk, int buf) {
        const int ksrc = chunk * BKB;
        #pragma unroll
        for (int i = 0; i < 2; i++) {
            int slot = tid + i * 256;
            int r = slot >> 3, q = slot & 7;
            int gr = row0 + r;
            cpa16z(smaddr(&As[buf][r][q * 8]),
                   g_a + (size_t)gr * KP + ksrc + q * 8, gr < Mend ? 16 : 0);
        }
        #pragma unroll
        for (int i = 0; i < 4; i++) {
            int slot = tid + i * 256;
            int r = slot >> 4, q = slot & 15;
            cpa16(smaddr(&Bs[buf][r][q * 8]),
                  wbase + (size_t)(ksrc + r) * KP + col0 + q * 8);
        }
        CPA_COMMIT();
    };

    issue(0, 0);
    issue(1, 1);
    #pragma unroll 1
    for (int c = 0; c < NCHUNK; c++) {
        const int buf = c & 1;
        if (c < NCHUNK - 1) CPA_WAIT(1);
        else                CPA_WAIT(0);
        __syncthreads();
        #pragma unroll
        for (int ks = 0; ks < 4; ks++) {
            const int kk = ks * 16;
            unsigned af[2][4], bf[2][4];
            #pragma unroll
            for (int mt = 0; mt < 2; mt++) {
                int r = wm + mt * 16 + (lane & 7) + (lane & 8);
                int cc = kk + ((lane & 16) ? 8 : 0);
                ldsm_x4(smaddr(&As[buf][r][cc]), af[mt][0], af[mt][1], af[mt][2], af[mt][3]);
            }
            #pragma unroll
            for (int nt = 0; nt < 2; nt++) {
                int r = kk + (lane & 7) + (lane & 8);
                int cc = wn + nt * 16 + ((lane & 16) ? 8 : 0);
                ldsm_x4_t(smaddr(&Bs[buf][r][cc]), bf[nt][0], bf[nt][1], bf[nt][2], bf[nt][3]);
            }
            #pragma unroll
            for (int mt = 0; mt < 2; mt++)
                #pragma unroll
                for (int j = 0; j < 4; j++)
                    mma_f16(acc[mt][j], af[mt], bf[j >> 1][(j & 1) * 2],
                            bf[j >> 1][(j & 1) * 2 + 1]);
        }
        __syncthreads();
        if (c + NSTAGE < NCHUNK) issue(c + NSTAGE, buf);
    }
    // epilogue: optional dinv scaling; fp16 stores into padded g_hs
    const int gID = lane >> 2, tig = lane & 3;
    #pragma unroll
    for (int mt = 0; mt < 2; mt++) {
        #pragma unroll
        for (int half = 0; half < 2; half++) {
            int gr = row0 + wm + mt * 16 + gID + half * 8;
            if (gr >= Mend) continue;
            float dv = scale ? g_dinv[gr] : 1.0f;
            #pragma unroll
            for (int j = 0; j < 4; j++) {
                int gc = col0 + wn + j * 8 + tig * 2;
                __half2 v = __floats2half2_rn(acc[mt][j][half * 2 + 0] * dv,
                                              acc[mt][j][half * 2 + 1] * dv);
                *(__half2*)&g_hs[(size_t)gr * HSP + gc] = v;
            }
        }
    }
}

// ---------------- warp-per-node gather + bias + act ------------------------
__device__ __forceinline__ void acc8(float* acc, uint4 u) {
    float2 f;
    f = __half22float2(*(__half2*)&u.x); acc[0] += f.x; acc[1] += f.y;
    f = __half22float2(*((__half2*)&u.x + 1)); acc[2] += f.x; acc[3] += f.y;
    f = __half22float2(*(__half2*)&u.z); acc[4] += f.x; acc[5] += f.y;
    f = __half22float2(*((__half2*)&u.z + 1)); acc[6] += f.x; acc[7] += f.y;
}
__device__ __forceinline__ void acc8w(float* acc, uint4 u, float w) {
    float2 f;
    f = __half22float2(*(__half2*)&u.x);
    acc[0] = fmaf(w, f.x, acc[0]); acc[1] = fmaf(w, f.y, acc[1]);
    f = __half22float2(*((__half2*)&u.x + 1));
    acc[2] = fmaf(w, f.x, acc[2]); acc[3] = fmaf(w, f.y, acc[3]);
    f = __half22float2(*(__half2*)&u.z);
    acc[4] = fmaf(w, f.x, acc[4]); acc[5] = fmaf(w, f.y, acc[5]);
    f = __half22float2(*((__half2*)&u.z + 1));
    acc[6] = fmaf(w, f.x, acc[6]); acc[7] = fmaf(w, f.y, acc[7]);
}

__global__ __launch_bounds__(256) void gather_k(int last, int layer, int prescaled,
                                                float* __restrict__ out, int N) {
    const int warp = threadIdx.x >> 5;
    const int lane = threadIdx.x & 31;
    const int n = blockIdx.x * 8 + warp;
    if (n >= N) return;

    const uint4* hs4 = (const uint4*)g_hs;
    const float dv = g_dinv[n];
    const int start = g_rowstart[n];
    const int cnt   = g_cnt[n];

    float acc[8] = {0, 0, 0, 0, 0, 0, 0, 0};
    {
        uint4 u = __ldg(&hs4[(size_t)n * 32 + lane]);
        if (prescaled) acc8(acc, u); else acc8w(acc, u, dv);
    }
    for (int base = 0; base < cnt; base += 32) {
        int rem = cnt - base;
        int m = rem < 32 ? rem : 32;
        int myidx = (lane < m) ? __ldg(&g_csr[start + base + lane]) : 0;
        float myd = 0.0f;
        if (!prescaled && lane < m) myd = __ldg(&g_dinv[myidx]);
        #pragma unroll 4
        for (int j = 0; j < m; j++) {
            int s = __shfl_sync(0xffffffffu, myidx, j);
            uint4 u = __ldg(&hs4[(size_t)s * 32 + lane]);
            if (prescaled) {
                acc8(acc, u);
            } else {
                float w = __shfl_sync(0xffffffffu, myd, j);
                acc8w(acc, u, w);
            }
        }
    }
    const int c0 = lane * 8;
    const float4 bb0 = ((const float4*)(g_bpad + layer * HSP))[lane * 2];
    const float4 bb1 = ((const float4*)(g_bpad + layer * HSP))[lane * 2 + 1];
    float v[8];
    v[0] = dv * acc[0] + bb0.x;
    v[1] = dv * acc[1] + bb0.y;
    v[2] = dv * acc[2] + bb0.z;
    v[3] = dv * acc[3] + bb0.w;
    v[4] = dv * acc[4] + bb1.x;
    v[5] = dv * acc[5] + bb1.y;
    v[6] = dv * acc[6] + bb1.z;
    v[7] = dv * acc[7] + bb1.w;

    if (!last) {
        float r[8];
        #pragma unroll
        for (int i = 0; i < 8; i++)
            r[i] = (c0 + i < HID && v[i] > 0.0f) ? v[i] : 0.0f;
        uint4 u;
        __half2 h;
        h = __floats2half2_rn(r[0], r[1]); u.x = *(unsigned*)&h;
        h = __floats2half2_rn(r[2], r[3]); u.y = *(unsigned*)&h;
        h = __floats2half2_rn(r[4], r[5]); u.z = *(unsigned*)&h;
        h = __floats2half2_rn(r[6], r[7]); u.w = *(unsigned*)&h;
        *(uint4*)(g_a + (size_t)n * KP + c0) = u;
        return;
    }
    float m = -INFINITY;
    #pragma unroll
    for (int i = 0; i < 8; i++)
        if (c0 + i < HID) m = fmaxf(m, v[i]);
    #pragma unroll
    for (int o = 16; o > 0; o >>= 1) m = fmaxf(m, __shfl_xor_sync(0xffffffffu, m, o));
    float s = 0.0f;
    #pragma unroll
    for (int i = 0; i < 8; i++)
        if (c0 + i < HID) s += expf(v[i] - m);
    #pragma unroll
    for (int o = 16; o > 0; o >>= 1) s += __shfl_xor_sync(0xffffffffu, s, o);
    const float lse = logf(s);
    #pragma unroll
    for (int i = 0; i < 8; i++)
        if (c0 + i < HID) out[(size_t)n * HID + c0 + i] = v[i] - m - lse;
}

// ---------------- launch ----------------------------------------------------
extern "C" void kernel_launch(void* const* d_in, const int* in_sizes, int n_in,
                              void* d_out, int out_size) {
    const float* x  = (const float*)d_in[0];
    const int*   ei = (const int*)  d_in[1];
    const float* W1 = (const float*)d_in[2];
    const float* b1 = (const float*)d_in[3];
    const float* W2 = (const float*)d_in[4];
    const float* b2 = (const float*)d_in[5];
    const float* W3 = (const float*)d_in[6];
    const float* b3 = (const float*)d_in[7];
    const float* W4 = (const float*)d_in[8];
    const float* b4 = (const float*)d_in[9];
    float* out = (float*)d_out;

    const int HIDc = in_sizes[3];                 // 246
    const int F_IN = in_sizes[2] / HIDc;          // 256
    const int N    = in_sizes[0] / F_IN;          // 50000
    const int E    = in_sizes[1] / 2;             // 320000

    cudaFuncSetAttribute(gemm_tc_k,
                         cudaFuncAttributeMaxDynamicSharedMemorySize, GEMM_SMEM);

    const int gath_grid = (N + 7) / 8;            // 6250
    int nb = (N + 255) / 256;
    int nwords = (2 * E < 4096) ? 2 * E : 4096;
    int wblk = (4 * KP * KP + 255) / 256;         // 1024

    // launches 0,1: conversions
    conv_x_k<<<(N * F_IN / 4 + 255) / 256, 256>>>(x, N * F_IN / 4);
    conv_w4_k<<<wblk, 256>>>(W1, W2, W3, W4, b1, b2, b3, b4, F_IN, wblk);

    // launches 2,3: layer-0 GEMM split (keeps gemm under the ncu window)
    const int Mhalf = ((N / 2) + BM - 1) / BM * BM;   // 25024
    dim3 g0a(2, Mhalf / BM);
    dim3 g0b(2, (N - Mhalf + BM - 1) / BM);
    gemm_tc_k<<<g0a, 256, GEMM_SMEM>>>(0, Mhalf, 0, 0);
    gemm_tc_k<<<g0b, 256, GEMM_SMEM>>>(Mhalf, N, 0, 0);

    // edge preprocessing -> CSR (+ dinv)
    detect_zero_k<<<nb, 256>>>(ei, nwords, N);
    convert_count_k<<<(E + 255) / 256, 256>>>(ei, E);
    scan1_k<<<nb, 256>>>(N);
    scan2_k<<<1, 256>>>(nb);
    scan3_dinv_k<<<nb, 256>>>(N);
    fill_csr_k<<<(E + 255) / 256, 256>>>(E);

    // layer 0 gather: hs unscaled -> per-edge dinv weighting
    gather_k<<<gath_grid, 256>>>(0, 0, 0, out, N);

    // layers 1-3: dinv folded into GEMM epilogue, plain-sum gather
    dim3 ggrid(2, (N + BM - 1) / BM);
    for (int layer = 1; layer < 4; layer++) {
        gemm_tc_k<<<ggrid, 256, GEMM_SMEM>>>(0, N, layer, 1);
        gather_k<<<gath_grid, 256>>>(layer == 3 ? 1 : 0, layer, 1, out, N);
    }
    (void)n_in; (void)out_size;
}

// round 15
// speedup vs baseline: 1.0681x; 1.0681x over previous
#include <cuda_runtime.h>
#include <cuda_bf16.h>
#include <cuda_fp16.h>
#include <math.h>
#include <stdint.h>

#define HID   246
#define NMAX  50000
#define EMAX  320000
#define KP    256            // padded K (activation row stride, halves)
#define HSP   256            // padded g_hs row stride (halves)
#define NBLK  ((NMAX + 255) / 256)

// ---------------- device-global scratch (no allocation allowed) ------------
__device__ __align__(16) float g_dinv[NMAX];
__device__ __align__(16) __half g_hs[NMAX * HSP];     // GEMM out, fp16
__device__ __align__(16) __half g_a [NMAX * KP];      // activations, fp16
__device__ __align__(16) __half g_w [4 * KP * KP];    // W [k][n] padded, fp16
__device__ __align__(16) float g_bpad[4 * HSP];       // padded biases
__device__ int g_src[EMAX];
__device__ int g_dst[EMAX];
__device__ int g_cnt[NMAX];
__device__ int g_rsI[NMAX];
__device__ int g_rowstart[NMAX];
__device__ int g_cursor[NMAX];
__device__ int g_csr[EMAX];
__device__ int g_bsum[NBLK];
__device__ int g_boff[NBLK];
__device__ int g_is64;

// ---------------- helpers ---------------------------------------------------
__device__ __forceinline__ unsigned smaddr(const void* p) {
    return (unsigned)__cvta_generic_to_shared(p);
}
__device__ __forceinline__ void ldsm_x4(unsigned a, unsigned& r0, unsigned& r1,
                                        unsigned& r2, unsigned& r3) {
    asm volatile("ldmatrix.sync.aligned.m8n8.x4.shared.b16 {%0,%1,%2,%3}, [%4];"
                 : "=r"(r0), "=r"(r1), "=r"(r2), "=r"(r3) : "r"(a));
}
__device__ __forceinline__ void ldsm_x4_t(unsigned a, unsigned& r0, unsigned& r1,
                                          unsigned& r2, unsigned& r3) {
    asm volatile("ldmatrix.sync.aligned.m8n8.x4.trans.shared.b16 {%0,%1,%2,%3}, [%4];"
                 : "=r"(r0), "=r"(r1), "=r"(r2), "=r"(r3) : "r"(a));
}
__device__ __forceinline__ void mma_f16(float* c, const unsigned* a, unsigned b0, unsigned b1) {
    asm volatile("mma.sync.aligned.m16n8k16.row.col.f32.f16.f16.f32 "
                 "{%0,%1,%2,%3}, {%4,%5,%6,%7}, {%8,%9}, {%0,%1,%2,%3};"
                 : "+f"(c[0]), "+f"(c[1]), "+f"(c[2]), "+f"(c[3])
                 : "r"(a[0]), "r"(a[1]), "r"(a[2]), "r"(a[3]), "r"(b0), "r"(b1));
}
__device__ __forceinline__ void cpa16(unsigned dst, const void* src) {
    asm volatile("cp.async.cg.shared.global [%0], [%1], 16;" :: "r"(dst), "l"(src));
}
__device__ __forceinline__ void cpa16z(unsigned dst, const void* src, int srcbytes) {
    asm volatile("cp.async.cg.shared.global [%0], [%1], 16, %2;"
                 :: "r"(dst), "l"(src), "r"(srcbytes));
}
#define CPA_COMMIT() asm volatile("cp.async.commit_group;" ::: "memory")
#define CPA_WAIT(n)  asm volatile("cp.async.wait_group %0;" :: "n"(n) : "memory")

// ---------------- conversions ----------------------------------------------
__global__ void conv_x_k(const float* __restrict__ x, int total4) {
    int i = blockIdx.x * blockDim.x + threadIdx.x;
    if (i >= total4) return;
    float4 v = ((const float4*)x)[i];
    __half2 h01 = __floats2half2_rn(v.x, v.y);
    __half2 h23 = __floats2half2_rn(v.z, v.w);
    uint2 u;
    u.x = *(unsigned*)&h01;
    u.y = *(unsigned*)&h23;
    ((uint2*)g_a)[i] = u;
}
// last block also pads the biases
__global__ void conv_w4_k(const float* __restrict__ W1, const float* __restrict__ W2,
                          const float* __restrict__ W3, const float* __restrict__ W4,
                          const float* __restrict__ b1, const float* __restrict__ b2,
                          const float* __restrict__ b3, const float* __restrict__ b4,
                          int K1, int nblk) {
    if (blockIdx.x == nblk - 1) {
        int c = threadIdx.x;
        const float* bs[4] = {b1, b2, b3, b4};
        #pragma unroll
        for (int l = 0; l < 4; l++)
            g_bpad[l * HSP + c] = (c < HID) ? bs[l][c] : 0.0f;
    }
    int i = blockIdx.x * blockDim.x + threadIdx.x;
    if (i >= 4 * KP * KP) return;
    int layer = i >> 16;
    int j = i & 0xFFFF;
    int r = j >> 8, c = j & 255;
    const float* W = (layer == 0) ? W1 : (layer == 1) ? W2 : (layer == 2) ? W3 : W4;
    int K = (layer == 0) ? K1 : HID;
    float v = (r < K && c < HID) ? W[r * HID + c] : 0.0f;
    g_w[i] = __float2half(v);
}

// ---------------- edge preprocessing ---------------------------------------
__global__ void detect_zero_k(const int* __restrict__ w, int nwords, int N) {
    int i = blockIdx.x * blockDim.x + threadIdx.x;
    if (i < N) g_cnt[i] = 0;
    if (blockIdx.x == 0) {
        __shared__ int any;
        if (threadIdx.x == 0) any = 0;
        __syncthreads();
        for (int j = 2 * threadIdx.x + 1; j < nwords; j += 2 * blockDim.x)
            if (w[j] != 0) any = 1;
        __syncthreads();
        if (threadIdx.x == 0) g_is64 = (any == 0) ? 1 : 0;
    }
}
__global__ void convert_count_k(const int* __restrict__ w, int E) {
    int i = blockIdx.x * blockDim.x + threadIdx.x;
    if (i >= E) return;
    int s, d;
    if (g_is64) { s = w[2 * i]; d = w[2 * (E + i)]; }
    else        { s = w[i];     d = w[E + i]; }
    g_src[i] = s;
    g_dst[i] = d;
    atomicAdd(&g_cnt[d], 1);
}
__global__ void scan1_k(int N) {
    __shared__ int sh[256];
    int i = blockIdx.x * 256 + threadIdx.x;
    int v = (i < N) ? g_cnt[i] : 0;
    sh[threadIdx.x] = v;
    __syncthreads();
    for (int o = 1; o < 256; o <<= 1) {
        int t = (threadIdx.x >= o) ? sh[threadIdx.x - o] : 0;
        __syncthreads();
        sh[threadIdx.x] += t;
        __syncthreads();
    }
    if (i < N) g_rsI[i] = sh[threadIdx.x];
    if (threadIdx.x == 255) g_bsum[blockIdx.x] = sh[255];
}
__global__ void scan2_k(int NB) {
    __shared__ int sh[256];
    int v = (threadIdx.x < NB) ? g_bsum[threadIdx.x] : 0;
    sh[threadIdx.x] = v;
    __syncthreads();
    for (int o = 1; o < 256; o <<= 1) {
        int t = (threadIdx.x >= o) ? sh[threadIdx.x - o] : 0;
        __syncthreads();
        sh[threadIdx.x] += t;
        __syncthreads();
    }
    if (threadIdx.x < NB) g_boff[threadIdx.x] = sh[threadIdx.x] - v;
}
__global__ void scan3_dinv_k(int N) {
    int i = blockIdx.x * blockDim.x + threadIdx.x;
    if (i >= N) return;
    int cnt = g_cnt[i];
    int ex = g_rsI[i] - cnt + g_boff[i >> 8];
    g_rowstart[i] = ex;
    g_cursor[i]   = ex;
    g_dinv[i]     = rsqrtf((float)(cnt + 1));
}
__global__ void fill_csr_k(int E) {
    int e = blockIdx.x * blockDim.x + threadIdx.x;
    if (e >= E) return;
    int d = g_dst[e];
    int pos = atomicAdd(&g_cursor[d], 1);
    g_csr[pos] = g_src[e];
}

// ---------------- fp16 tensor-core GEMM (R13 config: 128x128, 3-stage) -----
#define BM 128
#define BN 128
#define BKB 64
#define NCHUNK 4
#define NSTAGE 3
#define A_STRIDE 72
#define B_STRIDE 136
#define A_ST_BYTES (BM * A_STRIDE * 2)                  // 18432
#define B_ST_BYTES (BKB * B_STRIDE * 2)                 // 17408
#define GEMM_SMEM (NSTAGE * (A_ST_BYTES + B_ST_BYTES))  // 107520

__global__ __launch_bounds__(256, 2) void gemm_tc_k(int Mstart, int Mend,
                                                    int layer, int scale) {
    extern __shared__ char dsm[];
    __half (*As)[BM][A_STRIDE] = (__half (*)[BM][A_STRIDE])dsm;
    __half (*Bs)[BKB][B_STRIDE] = (__half (*)[BKB][B_STRIDE])(dsm + NSTAGE * A_ST_BYTES);
    const int tid  = threadIdx.x;
    const int lane = tid & 31;
    const int wid  = tid >> 5;
    const int wm   = (wid & 3) * 32;
    const int wn   = (wid >> 2) * 64;
    const int row0 = Mstart + blockIdx.y * BM;
    const int col0 = blockIdx.x * BN;
    const __half* wbase = g_w + (size_t)layer * KP * KP;

    float acc[2][8][4];
    #pragma unroll
    for (int a = 0; a < 2; a++)
        #pragma unroll
        for (int b = 0; b < 8; b++)
            #pragma unroll
            for (int c = 0; c < 4; c++) acc[a][b][c] = 0.0f;

    auto issue = [&](int chunk, int buf) {
        const int ksrc = chunk * BKB;
        #pragma unroll
        for (int i = 0; i < 4; i++) {
            int slot = tid + i * 256;
            int r = slot >> 3, q = slot & 7;
            int gr = row0 + r;
            cpa16z(smaddr(&As[buf][r][q * 8]),
                   g_a + (size_t)gr * KP + ksrc + q * 8, gr < Mend ? 16 : 0);
        }
        #pragma unroll
        for (int i = 0; i < 4; i++) {
            int slot = tid + i * 256;
            int r = slot >> 4, q = slot & 15;
            cpa16(smaddr(&Bs[buf][r][q * 8]),
                  wbase + (size_t)(ksrc + r) * KP + col0 + q * 8);
        }
        CPA_COMMIT();
    };

    issue(0, 0);
    issue(1, 1);
    issue(2, 2);
    #pragma unroll 1
    for (int c = 0; c < NCHUNK; c++) {
        const int buf = c % NSTAGE;
        if (c <= NCHUNK - 3)      CPA_WAIT(2);
        else if (c == NCHUNK - 2) CPA_WAIT(1);
        else                      CPA_WAIT(0);
        __syncthreads();
        #pragma unroll
        for (int ks = 0; ks < 4; ks++) {
            const int kk = ks * 16;
            unsigned af[2][4], bf[4][4];
            #pragma unroll
            for (int mt = 0; mt < 2; mt++) {
                int r = wm + mt * 16 + (lane & 7) + (lane & 8);
                int cc = kk + ((lane & 16) ? 8 : 0);
                ldsm_x4(smaddr(&As[buf][r][cc]), af[mt][0], af[mt][1], af[mt][2], af[mt][3]);
            }
            #pragma unroll
            for (int nt = 0; nt < 4; nt++) {
                int r = kk + (lane & 7) + (lane & 8);
                int cc = wn + nt * 16 + ((lane & 16) ? 8 : 0);
                ldsm_x4_t(smaddr(&Bs[buf][r][cc]), bf[nt][0], bf[nt][1], bf[nt][2], bf[nt][3]);
            }
            #pragma unroll
            for (int mt = 0; mt < 2; mt++)
                #pragma unroll
                for (int j = 0; j < 8; j++)
                    mma_f16(acc[mt][j], af[mt], bf[j >> 1][(j & 1) * 2],
                            bf[j >> 1][(j & 1) * 2 + 1]);
        }
        __syncthreads();
        if (c + NSTAGE < NCHUNK) issue(c + NSTAGE, buf);
    }
    const int gID = lane >> 2, tig = lane & 3;
    #pragma unroll
    for (int mt = 0; mt < 2; mt++) {
        #pragma unroll
        for (int half = 0; half < 2; half++) {
            int gr = row0 + wm + mt * 16 + gID + half * 8;
            if (gr >= Mend) continue;
            float dv = scale ? g_dinv[gr] : 1.0f;
            #pragma unroll
            for (int j = 0; j < 8; j++) {
                int gc = col0 + wn + j * 8 + tig * 2;
                __half2 v = __floats2half2_rn(acc[mt][j][half * 2 + 0] * dv,
                                              acc[mt][j][half * 2 + 1] * dv);
                *(__half2*)&g_hs[(size_t)gr * HSP + gc] = v;
            }
        }
    }
}

// ---------------- warp-per-node gather + bias + act ------------------------
__device__ __forceinline__ void acc8(float* acc, uint4 u) {
    float2 f;
    f = __half22float2(*(__half2*)&u.x); acc[0] += f.x; acc[1] += f.y;
    f = __half22float2(*((__half2*)&u.x + 1)); acc[2] += f.x; acc[3] += f.y;
    f = __half22float2(*(__half2*)&u.z); acc[4] += f.x; acc[5] += f.y;
    f = __half22float2(*((__half2*)&u.z + 1)); acc[6] += f.x; acc[7] += f.y;
}
__device__ __forceinline__ void acc8w(float* acc, uint4 u, float w) {
    float2 f;
    f = __half22float2(*(__half2*)&u.x);
    acc[0] = fmaf(w, f.x, acc[0]); acc[1] = fmaf(w, f.y, acc[1]);
    f = __half22float2(*((__half2*)&u.x + 1));
    acc[2] = fmaf(w, f.x, acc[2]); acc[3] = fmaf(w, f.y, acc[3]);
    f = __half22float2(*(__half2*)&u.z);
    acc[4] = fmaf(w, f.x, acc[4]); acc[5] = fmaf(w, f.y, acc[5]);
    f = __half22float2(*((__half2*)&u.z + 1));
    acc[6] = fmaf(w, f.x, acc[6]); acc[7] = fmaf(w, f.y, acc[7]);
}

__global__ __launch_bounds__(256) void gather_k(int last, int layer, int prescaled,
                                                float* __restrict__ out, int N) {
    const int warp = threadIdx.x >> 5;
    const int lane = threadIdx.x & 31;
    const int n = blockIdx.x * 8 + warp;
    if (n >= N) return;

    const uint4* hs4 = (const uint4*)g_hs;
    const float dv = g_dinv[n];
    const int start = g_rowstart[n];
    const int cnt   = g_cnt[n];

    float acc[8] = {0, 0, 0, 0, 0, 0, 0, 0};
    {
        uint4 u = __ldg(&hs4[(size_t)n * 32 + lane]);
        if (prescaled) acc8(acc, u); else acc8w(acc, u, dv);
    }
    for (int base = 0; base < cnt; base += 32) {
        int rem = cnt - base;
        int m = rem < 32 ? rem : 32;
        int myidx = (lane < m) ? __ldg(&g_csr[start + base + lane]) : 0;
        float myd = 0.0f;
        if (!prescaled && lane < m) myd = __ldg(&g_dinv[myidx]);
        #pragma unroll 4
        for (int j = 0; j < m; j++) {
            int s = __shfl_sync(0xffffffffu, myidx, j);
            uint4 u = __ldg(&hs4[(size_t)s * 32 + lane]);
            if (prescaled) {
                acc8(acc, u);
            } else {
                float w = __shfl_sync(0xffffffffu, myd, j);
                acc8w(acc, u, w);
            }
        }
    }
    const int c0 = lane * 8;
    const float4 bb0 = ((const float4*)(g_bpad + layer * HSP))[lane * 2];
    const float4 bb1 = ((const float4*)(g_bpad + layer * HSP))[lane * 2 + 1];
    float v[8];
    v[0] = dv * acc[0] + bb0.x;
    v[1] = dv * acc[1] + bb0.y;
    v[2] = dv * acc[2] + bb0.z;
    v[3] = dv * acc[3] + bb0.w;
    v[4] = dv * acc[4] + bb1.x;
    v[5] = dv * acc[5] + bb1.y;
    v[6] = dv * acc[6] + bb1.z;
    v[7] = dv * acc[7] + bb1.w;

    if (!last) {
        float r[8];
        #pragma unroll
        for (int i = 0; i < 8; i++)
            r[i] = (c0 + i < HID && v[i] > 0.0f) ? v[i] : 0.0f;
        uint4 u;
        __half2 h;
        h = __floats2half2_rn(r[0], r[1]); u.x = *(unsigned*)&h;
        h = __floats2half2_rn(r[2], r[3]); u.y = *(unsigned*)&h;
        h = __floats2half2_rn(r[4], r[5]); u.z = *(unsigned*)&h;
        h = __floats2half2_rn(r[6], r[7]); u.w = *(unsigned*)&h;
        *(uint4*)(g_a + (size_t)n * KP + c0) = u;
        return;
    }
    float m = -INFINITY;
    #pragma unroll
    for (int i = 0; i < 8; i++)
        if (c0 + i < HID) m = fmaxf(m, v[i]);
    #pragma unroll
    for (int o = 16; o > 0; o >>= 1) m = fmaxf(m, __shfl_xor_sync(0xffffffffu, m, o));
    float s = 0.0f;
    #pragma unroll
    for (int i = 0; i < 8; i++)
        if (c0 + i < HID) s += expf(v[i] - m);
    #pragma unroll
    for (int o = 16; o > 0; o >>= 1) s += __shfl_xor_sync(0xffffffffu, s, o);
    const float lse = logf(s);
    #pragma unroll
    for (int i = 0; i < 8; i++)
        if (c0 + i < HID) out[(size_t)n * HID + c0 + i] = v[i] - m - lse;
}

// ---------------- launch ----------------------------------------------------
extern "C" void kernel_launch(void* const* d_in, const int* in_sizes, int n_in,
                              void* d_out, int out_size) {
    const float* x  = (const float*)d_in[0];
    const int*   ei = (const int*)  d_in[1];
    const float* W1 = (const float*)d_in[2];
    const float* b1 = (const float*)d_in[3];
    const float* W2 = (const float*)d_in[4];
    const float* b2 = (const float*)d_in[5];
    const float* W3 = (const float*)d_in[6];
    const float* b3 = (const float*)d_in[7];
    const float* W4 = (const float*)d_in[8];
    const float* b4 = (const float*)d_in[9];
    float* out = (float*)d_out;

    const int HIDc = in_sizes[3];                 // 246
    const int F_IN = in_sizes[2] / HIDc;          // 256
    const int N    = in_sizes[0] / F_IN;          // 50000
    const int E    = in_sizes[1] / 2;             // 320000

    // one-time host objects (not device memory; allowed)
    static cudaStream_t s2 = nullptr;
    static cudaEvent_t evFork = nullptr, evJoin = nullptr;
    if (!s2) {
        cudaStreamCreateWithFlags(&s2, cudaStreamNonBlocking);
        cudaEventCreateWithFlags(&evFork, cudaEventDisableTiming);
        cudaEventCreateWithFlags(&evJoin, cudaEventDisableTiming);
        cudaFuncSetAttribute(gemm_tc_k,
                             cudaFuncAttributeMaxDynamicSharedMemorySize, GEMM_SMEM);
    }

    const int gath_grid = (N + 7) / 8;            // 6250
    int nb = (N + 255) / 256;
    int nwords = (2 * E < 4096) ? 2 * E : 4096;
    int wblk = (4 * KP * KP + 255) / 256;         // 1024

    // fork: s2 joins the capture/stream via event
    cudaEventRecord(evFork, 0);
    cudaStreamWaitEvent(s2, evFork, 0);

    // ---- branch A (s2): conversions + layer-0 GEMM (graph-independent) ----
    conv_x_k<<<(N * F_IN / 4 + 255) / 256, 256, 0, s2>>>(x, N * F_IN / 4);
    conv_w4_k<<<wblk, 256, 0, s2>>>(W1, W2, W3, W4, b1, b2, b3, b4, F_IN, wblk);
    const int Mhalf = ((N / 2) + BM - 1) / BM * BM;
    dim3 g0a(2, Mhalf / BM);
    dim3 g0b(2, (N - Mhalf + BM - 1) / BM);
    gemm_tc_k<<<g0a, 256, GEMM_SMEM, s2>>>(0, Mhalf, 0, 0);
    gemm_tc_k<<<g0b, 256, GEMM_SMEM, s2>>>(Mhalf, N, 0, 0);
    cudaEventRecord(evJoin, s2);

    // ---- branch B (default stream): edge preprocessing -> CSR (+ dinv) ----
    detect_zero_k<<<nb, 256>>>(ei, nwords, N);
    convert_count_k<<<(E + 255) / 256, 256>>>(ei, E);
    scan1_k<<<nb, 256>>>(N);
    scan2_k<<<1, 256>>>(nb);
    scan3_dinv_k<<<nb, 256>>>(N);
    fill_csr_k<<<(E + 255) / 256, 256>>>(E);

    // join: gather0 needs both branches
    cudaStreamWaitEvent(0, evJoin, 0);

    // layer 0 gather: hs unscaled -> per-edge dinv weighting
    gather_k<<<gath_grid, 256>>>(0, 0, 0, out, N);

    // layers 1-3: dinv folded into GEMM epilogue, plain-sum gather
    dim3 ggrid(2, (N + BM - 1) / BM);
    for (int layer = 1; layer < 4; layer++) {
        gemm_tc_k<<<ggrid, 256, GEMM_SMEM>>>(0, N, layer, 1);
        gather_k<<<gath_grid, 256>>>(layer == 3 ? 1 : 0, layer, 1, out, N);
    }
    (void)n_in; (void)out_size;
}

// round 16
// speedup vs baseline: 1.0874x; 1.0181x over previous
#include <cuda_runtime.h>
#include <cuda_bf16.h>
#include <cuda_fp16.h>
#include <math.h>
#include <stdint.h>

#define HID   246
#define NMAX  50000
#define EMAX  320000
#define KP    256            // padded K (activation row stride, halves)
#define HSP   256            // padded g_hs row stride (halves)
#define NBLK  ((NMAX + 255) / 256)

// ---------------- device-global scratch (no allocation allowed) ------------
__device__ __align__(16) float g_dinv[NMAX];
__device__ __align__(16) __half g_hs[NMAX * HSP];     // GEMM out, fp16
__device__ __align__(16) __half g_a [NMAX * KP];      // activations, fp16
__device__ __align__(16) __half g_w [4 * KP * KP];    // W [k][n] padded, fp16
__device__ __align__(16) float g_bpad[4 * HSP];       // padded biases
__device__ int g_src[EMAX];
__device__ int g_dst[EMAX];
__device__ int g_cnt[NMAX];
__device__ int g_rsI[NMAX];
__device__ int g_rowstart[NMAX];
__device__ int g_cursor[NMAX];
__device__ int g_csr[EMAX];
__device__ int g_bsum[NBLK];
__device__ int g_boff[NBLK];
__device__ int g_is64;

// ---------------- helpers ---------------------------------------------------
__device__ __forceinline__ unsigned smaddr(const void* p) {
    return (unsigned)__cvta_generic_to_shared(p);
}
__device__ __forceinline__ void ldsm_x4(unsigned a, unsigned& r0, unsigned& r1,
                                        unsigned& r2, unsigned& r3) {
    asm volatile("ldmatrix.sync.aligned.m8n8.x4.shared.b16 {%0,%1,%2,%3}, [%4];"
                 : "=r"(r0), "=r"(r1), "=r"(r2), "=r"(r3) : "r"(a));
}
__device__ __forceinline__ void ldsm_x4_t(unsigned a, unsigned& r0, unsigned& r1,
                                          unsigned& r2, unsigned& r3) {
    asm volatile("ldmatrix.sync.aligned.m8n8.x4.trans.shared.b16 {%0,%1,%2,%3}, [%4];"
                 : "=r"(r0), "=r"(r1), "=r"(r2), "=r"(r3) : "r"(a));
}
__device__ __forceinline__ void mma_f16(float* c, const unsigned* a, unsigned b0, unsigned b1) {
    asm volatile("mma.sync.aligned.m16n8k16.row.col.f32.f16.f16.f32 "
                 "{%0,%1,%2,%3}, {%4,%5,%6,%7}, {%8,%9}, {%0,%1,%2,%3};"
                 : "+f"(c[0]), "+f"(c[1]), "+f"(c[2]), "+f"(c[3])
                 : "r"(a[0]), "r"(a[1]), "r"(a[2]), "r"(a[3]), "r"(b0), "r"(b1));
}
__device__ __forceinline__ void cpa16(unsigned dst, const void* src) {
    asm volatile("cp.async.cg.shared.global [%0], [%1], 16;" :: "r"(dst), "l"(src));
}
__device__ __forceinline__ void cpa16z(unsigned dst, const void* src, int srcbytes) {
    asm volatile("cp.async.cg.shared.global [%0], [%1], 16, %2;"
                 :: "r"(dst), "l"(src), "r"(srcbytes));
}
#define CPA_COMMIT() asm volatile("cp.async.commit_group;" ::: "memory")
#define CPA_WAIT(n)  asm volatile("cp.async.wait_group %0;" :: "n"(n) : "memory")

// ---------------- conversions ----------------------------------------------
__global__ void conv_x_k(const float* __restrict__ x, int total4) {
    int i = blockIdx.x * blockDim.x + threadIdx.x;
    if (i >= total4) return;
    float4 v = ((const float4*)x)[i];
    __half2 h01 = __floats2half2_rn(v.x, v.y);
    __half2 h23 = __floats2half2_rn(v.z, v.w);
    uint2 u;
    u.x = *(unsigned*)&h01;
    u.y = *(unsigned*)&h23;
    ((uint2*)g_a)[i] = u;
}
// last block also pads the biases
__global__ void conv_w4_k(const float* __restrict__ W1, const float* __restrict__ W2,
                          const float* __restrict__ W3, const float* __restrict__ W4,
                          const float* __restrict__ b1, const float* __restrict__ b2,
                          const float* __restrict__ b3, const float* __restrict__ b4,
                          int K1, int nblk) {
    if (blockIdx.x == nblk - 1) {
        int c = threadIdx.x;
        const float* bs[4] = {b1, b2, b3, b4};
        #pragma unroll
        for (int l = 0; l < 4; l++)
            g_bpad[l * HSP + c] = (c < HID) ? bs[l][c] : 0.0f;
    }
    int i = blockIdx.x * blockDim.x + threadIdx.x;
    if (i >= 4 * KP * KP) return;
    int layer = i >> 16;
    int j = i & 0xFFFF;
    int r = j >> 8, c = j & 255;
    const float* W = (layer == 0) ? W1 : (layer == 1) ? W2 : (layer == 2) ? W3 : W4;
    int K = (layer == 0) ? K1 : HID;
    float v = (r < K && c < HID) ? W[r * HID + c] : 0.0f;
    g_w[i] = __float2half(v);
}

// ---------------- edge preprocessing ---------------------------------------
__global__ void detect_zero_k(const int* __restrict__ w, int nwords, int N) {
    int i = blockIdx.x * blockDim.x + threadIdx.x;
    if (i < N) g_cnt[i] = 0;
    if (blockIdx.x == 0) {
        __shared__ int any;
        if (threadIdx.x == 0) any = 0;
        __syncthreads();
        for (int j = 2 * threadIdx.x + 1; j < nwords; j += 2 * blockDim.x)
            if (w[j] != 0) any = 1;
        __syncthreads();
        if (threadIdx.x == 0) g_is64 = (any == 0) ? 1 : 0;
    }
}
__global__ void convert_count_k(const int* __restrict__ w, int E) {
    int i = blockIdx.x * blockDim.x + threadIdx.x;
    if (i >= E) return;
    int s, d;
    if (g_is64) { s = w[2 * i]; d = w[2 * (E + i)]; }
    else        { s = w[i];     d = w[E + i]; }
    g_src[i] = s;
    g_dst[i] = d;
    atomicAdd(&g_cnt[d], 1);
}
__global__ void scan1_k(int N) {
    __shared__ int sh[256];
    int i = blockIdx.x * 256 + threadIdx.x;
    int v = (i < N) ? g_cnt[i] : 0;
    sh[threadIdx.x] = v;
    __syncthreads();
    for (int o = 1; o < 256; o <<= 1) {
        int t = (threadIdx.x >= o) ? sh[threadIdx.x - o] : 0;
        __syncthreads();
        sh[threadIdx.x] += t;
        __syncthreads();
    }
    if (i < N) g_rsI[i] = sh[threadIdx.x];
    if (threadIdx.x == 255) g_bsum[blockIdx.x] = sh[255];
}
__global__ void scan2_k(int NB) {
    __shared__ int sh[256];
    int v = (threadIdx.x < NB) ? g_bsum[threadIdx.x] : 0;
    sh[threadIdx.x] = v;
    __syncthreads();
    for (int o = 1; o < 256; o <<= 1) {
        int t = (threadIdx.x >= o) ? sh[threadIdx.x - o] : 0;
        __syncthreads();
        sh[threadIdx.x] += t;
        __syncthreads();
    }
    if (threadIdx.x < NB) g_boff[threadIdx.x] = sh[threadIdx.x] - v;
}
__global__ void scan3_dinv_k(int N) {
    int i = blockIdx.x * blockDim.x + threadIdx.x;
    if (i >= N) return;
    int cnt = g_cnt[i];
    int ex = g_rsI[i] - cnt + g_boff[i >> 8];
    g_rowstart[i] = ex;
    g_cursor[i]   = ex;
    g_dinv[i]     = rsqrtf((float)(cnt + 1));
}
__global__ void fill_csr_k(int E) {
    int e = blockIdx.x * blockDim.x + threadIdx.x;
    if (e >= E) return;
    int d = g_dst[e];
    int pos = atomicAdd(&g_cursor[d], 1);
    g_csr[pos] = g_src[e];
}

// ---------------- fp16 tensor-core GEMM (128x128, 3-stage, Kc=64) ----------
#define BM 128
#define BN 128
#define BKB 64
#define NCHUNK 4
#define NSTAGE 3
#define A_STRIDE 72
#define B_STRIDE 136
#define A_ST_BYTES (BM * A_STRIDE * 2)                  // 18432
#define B_ST_BYTES (BKB * B_STRIDE * 2)                 // 17408
#define GEMM_SMEM (NSTAGE * (A_ST_BYTES + B_ST_BYTES))  // 107520

__global__ __launch_bounds__(256, 2) void gemm_tc_k(int Mstart, int Mend,
                                                    int layer, int scale) {
    extern __shared__ char dsm[];
    __half (*As)[BM][A_STRIDE] = (__half (*)[BM][A_STRIDE])dsm;
    __half (*Bs)[BKB][B_STRIDE] = (__half (*)[BKB][B_STRIDE])(dsm + NSTAGE * A_ST_BYTES);
    const int tid  = threadIdx.x;
    const int lane = tid & 31;
    const int wid  = tid >> 5;
    const int wm   = (wid & 3) * 32;
    const int wn   = (wid >> 2) * 64;
    const int row0 = Mstart + blockIdx.y * BM;
    const int col0 = blockIdx.x * BN;
    const __half* wbase = g_w + (size_t)layer * KP * KP;

    float acc[2][8][4];
    #pragma unroll
    for (int a = 0; a < 2; a++)
        #pragma unroll
        for (int b = 0; b < 8; b++)
            #pragma unroll
            for (int c = 0; c < 4; c++) acc[a][b][c] = 0.0f;

    auto issue = [&](int chunk, int buf) {
        const int ksrc = chunk * BKB;
        #pragma unroll
        for (int i = 0; i < 4; i++) {
            int slot = tid + i * 256;
            int r = slot >> 3, q = slot & 7;
            int gr = row0 + r;
            cpa16z(smaddr(&As[buf][r][q * 8]),
                   g_a + (size_t)gr * KP + ksrc + q * 8, gr < Mend ? 16 : 0);
        }
        #pragma unroll
        for (int i = 0; i < 4; i++) {
            int slot = tid + i * 256;
            int r = slot >> 4, q = slot & 15;
            cpa16(smaddr(&Bs[buf][r][q * 8]),
                  wbase + (size_t)(ksrc + r) * KP + col0 + q * 8);
        }
        CPA_COMMIT();
    };

    issue(0, 0);
    issue(1, 1);
    issue(2, 2);
    #pragma unroll 1
    for (int c = 0; c < NCHUNK; c++) {
        const int buf = c % NSTAGE;
        if (c <= NCHUNK - 3)      CPA_WAIT(2);
        else if (c == NCHUNK - 2) CPA_WAIT(1);
        else                      CPA_WAIT(0);
        __syncthreads();
        #pragma unroll
        for (int ks = 0; ks < 4; ks++) {
            const int kk = ks * 16;
            unsigned af[2][4], bf[4][4];
            #pragma unroll
            for (int mt = 0; mt < 2; mt++) {
                int r = wm + mt * 16 + (lane & 7) + (lane & 8);
                int cc = kk + ((lane & 16) ? 8 : 0);
                ldsm_x4(smaddr(&As[buf][r][cc]), af[mt][0], af[mt][1], af[mt][2], af[mt][3]);
            }
            #pragma unroll
            for (int nt = 0; nt < 4; nt++) {
                int r = kk + (lane & 7) + (lane & 8);
                int cc = wn + nt * 16 + ((lane & 16) ? 8 : 0);
                ldsm_x4_t(smaddr(&Bs[buf][r][cc]), bf[nt][0], bf[nt][1], bf[nt][2], bf[nt][3]);
            }
            #pragma unroll
            for (int mt = 0; mt < 2; mt++)
                #pragma unroll
                for (int j = 0; j < 8; j++)
                    mma_f16(acc[mt][j], af[mt], bf[j >> 1][(j & 1) * 2],
                            bf[j >> 1][(j & 1) * 2 + 1]);
        }
        __syncthreads();
        if (c + NSTAGE < NCHUNK) issue(c + NSTAGE, buf);
    }
    const int gID = lane >> 2, tig = lane & 3;
    #pragma unroll
    for (int mt = 0; mt < 2; mt++) {
        #pragma unroll
        for (int half = 0; half < 2; half++) {
            int gr = row0 + wm + mt * 16 + gID + half * 8;
            if (gr >= Mend) continue;
            float dv = scale ? g_dinv[gr] : 1.0f;
            #pragma unroll
            for (int j = 0; j < 8; j++) {
                int gc = col0 + wn + j * 8 + tig * 2;
                __half2 v = __floats2half2_rn(acc[mt][j][half * 2 + 0] * dv,
                                              acc[mt][j][half * 2 + 1] * dv);
                *(__half2*)&g_hs[(size_t)gr * HSP + gc] = v;
            }
        }
    }
}

// ---------------- warp-per-node gather + bias + act (node range) -----------
__device__ __forceinline__ void acc8(float* acc, uint4 u) {
    float2 f;
    f = __half22float2(*(__half2*)&u.x); acc[0] += f.x; acc[1] += f.y;
    f = __half22float2(*((__half2*)&u.x + 1)); acc[2] += f.x; acc[3] += f.y;
    f = __half22float2(*(__half2*)&u.z); acc[4] += f.x; acc[5] += f.y;
    f = __half22float2(*((__half2*)&u.z + 1)); acc[6] += f.x; acc[7] += f.y;
}
__device__ __forceinline__ void acc8w(float* acc, uint4 u, float w) {
    float2 f;
    f = __half22float2(*(__half2*)&u.x);
    acc[0] = fmaf(w, f.x, acc[0]); acc[1] = fmaf(w, f.y, acc[1]);
    f = __half22float2(*((__half2*)&u.x + 1));
    acc[2] = fmaf(w, f.x, acc[2]); acc[3] = fmaf(w, f.y, acc[3]);
    f = __half22float2(*(__half2*)&u.z);
    acc[4] = fmaf(w, f.x, acc[4]); acc[5] = fmaf(w, f.y, acc[5]);
    f = __half22float2(*((__half2*)&u.z + 1));
    acc[6] = fmaf(w, f.x, acc[6]); acc[7] = fmaf(w, f.y, acc[7]);
}

__global__ __launch_bounds__(256) void gather_k(int last, int layer, int prescaled,
                                                float* __restrict__ out,
                                                int nstart, int nend) {
    const int warp = threadIdx.x >> 5;
    const int lane = threadIdx.x & 31;
    const int n = nstart + blockIdx.x * 8 + warp;
    if (n >= nend) return;

    const uint4* hs4 = (const uint4*)g_hs;
    const float dv = g_dinv[n];
    const int start = g_rowstart[n];
    const int cnt   = g_cnt[n];

    float acc[8] = {0, 0, 0, 0, 0, 0, 0, 0};
    {
        uint4 u = __ldg(&hs4[(size_t)n * 32 + lane]);
        if (prescaled) acc8(acc, u); else acc8w(acc, u, dv);
    }
    for (int base = 0; base < cnt; base += 32) {
        int rem = cnt - base;
        int m = rem < 32 ? rem : 32;
        int myidx = (lane < m) ? __ldg(&g_csr[start + base + lane]) : 0;
        float myd = 0.0f;
        if (!prescaled && lane < m) myd = __ldg(&g_dinv[myidx]);
        #pragma unroll 4
        for (int j = 0; j < m; j++) {
            int s = __shfl_sync(0xffffffffu, myidx, j);
            uint4 u = __ldg(&hs4[(size_t)s * 32 + lane]);
            if (prescaled) {
                acc8(acc, u);
            } else {
                float w = __shfl_sync(0xffffffffu, myd, j);
                acc8w(acc, u, w);
            }
        }
    }
    const int c0 = lane * 8;
    const float4 bb0 = ((const float4*)(g_bpad + layer * HSP))[lane * 2];
    const float4 bb1 = ((const float4*)(g_bpad + layer * HSP))[lane * 2 + 1];
    float v[8];
    v[0] = dv * acc[0] + bb0.x;
    v[1] = dv * acc[1] + bb0.y;
    v[2] = dv * acc[2] + bb0.z;
    v[3] = dv * acc[3] + bb0.w;
    v[4] = dv * acc[4] + bb1.x;
    v[5] = dv * acc[5] + bb1.y;
    v[6] = dv * acc[6] + bb1.z;
    v[7] = dv * acc[7] + bb1.w;

    if (!last) {
        float r[8];
        #pragma unroll
        for (int i = 0; i < 8; i++)
            r[i] = (c0 + i < HID && v[i] > 0.0f) ? v[i] : 0.0f;
        uint4 u;
        __half2 h;
        h = __floats2half2_rn(r[0], r[1]); u.x = *(unsigned*)&h;
        h = __floats2half2_rn(r[2], r[3]); u.y = *(unsigned*)&h;
        h = __floats2half2_rn(r[4], r[5]); u.z = *(unsigned*)&h;
        h = __floats2half2_rn(r[6], r[7]); u.w = *(unsigned*)&h;
        *(uint4*)(g_a + (size_t)n * KP + c0) = u;
        return;
    }
    float m = -INFINITY;
    #pragma unroll
    for (int i = 0; i < 8; i++)
        if (c0 + i < HID) m = fmaxf(m, v[i]);
    #pragma unroll
    for (int o = 16; o > 0; o >>= 1) m = fmaxf(m, __shfl_xor_sync(0xffffffffu, m, o));
    float s = 0.0f;
    #pragma unroll
    for (int i = 0; i < 8; i++)
        if (c0 + i < HID) s += expf(v[i] - m);
    #pragma unroll
    for (int o = 16; o > 0; o >>= 1) s += __shfl_xor_sync(0xffffffffu, s, o);
    const float lse = logf(s);
    #pragma unroll
    for (int i = 0; i < 8; i++)
        if (c0 + i < HID) out[(size_t)n * HID + c0 + i] = v[i] - m - lse;
}

// ---------------- launch ----------------------------------------------------
extern "C" void kernel_launch(void* const* d_in, const int* in_sizes, int n_in,
                              void* d_out, int out_size) {
    const float* x  = (const float*)d_in[0];
    const int*   ei = (const int*)  d_in[1];
    const float* W1 = (const float*)d_in[2];
    const float* b1 = (const float*)d_in[3];
    const float* W2 = (const float*)d_in[4];
    const float* b2 = (const float*)d_in[5];
    const float* W3 = (const float*)d_in[6];
    const float* b3 = (const float*)d_in[7];
    const float* W4 = (const float*)d_in[8];
    const float* b4 = (const float*)d_in[9];
    float* out = (float*)d_out;

    const int HIDc = in_sizes[3];                 // 246
    const int F_IN = in_sizes[2] / HIDc;          // 256
    const int N    = in_sizes[0] / F_IN;          // 50000
    const int E    = in_sizes[1] / 2;             // 320000

    // one-time host objects (streams/events; not device memory)
    static cudaStream_t s2 = nullptr;
    static cudaEvent_t evFork = nullptr, evJoin = nullptr, evG0 = nullptr, evEnd = nullptr;
    static cudaEvent_t evMA[4], evMB[4];
    if (!s2) {
        cudaStreamCreateWithFlags(&s2, cudaStreamNonBlocking);
        cudaEventCreateWithFlags(&evFork, cudaEventDisableTiming);
        cudaEventCreateWithFlags(&evJoin, cudaEventDisableTiming);
        cudaEventCreateWithFlags(&evG0, cudaEventDisableTiming);
        cudaEventCreateWithFlags(&evEnd, cudaEventDisableTiming);
        for (int l = 0; l < 4; l++) {
            cudaEventCreateWithFlags(&evMA[l], cudaEventDisableTiming);
            cudaEventCreateWithFlags(&evMB[l], cudaEventDisableTiming);
        }
        cudaFuncSetAttribute(gemm_tc_k,
                             cudaFuncAttributeMaxDynamicSharedMemorySize, GEMM_SMEM);
    }

    int nb = (N + 255) / 256;
    int nwords = (2 * E < 4096) ? 2 * E : 4096;
    int wblk = (4 * KP * KP + 255) / 256;         // 1024

    const int Mh = ((N / 2) + BM - 1) / BM * BM;  // 25088 (row/node split)
    dim3 gA(2, Mh / BM);                          // rows [0, Mh)
    dim3 gB(2, (N - Mh + BM - 1) / BM);           // rows [Mh, N)
    const int gaA = (Mh + 7) / 8;                 // gather blocks, half A
    const int gaB = (N - Mh + 7) / 8;             // half B

    // fork: s2 joins via event
    cudaEventRecord(evFork, 0);
    cudaStreamWaitEvent(s2, evFork, 0);

    // ---- branch A (s2): conversions + layer-0 GEMM ----
    conv_x_k<<<(N * F_IN / 4 + 255) / 256, 256, 0, s2>>>(x, N * F_IN / 4);
    conv_w4_k<<<wblk, 256, 0, s2>>>(W1, W2, W3, W4, b1, b2, b3, b4, F_IN, wblk);
    gemm_tc_k<<<gA, 256, GEMM_SMEM, s2>>>(0, Mh, 0, 0);
    gemm_tc_k<<<gB, 256, GEMM_SMEM, s2>>>(Mh, N, 0, 0);
    cudaEventRecord(evJoin, s2);

    // ---- branch B (stream 0): edge preprocessing -> CSR (+ dinv) ----
    detect_zero_k<<<nb, 256>>>(ei, nwords, N);
    convert_count_k<<<(E + 255) / 256, 256>>>(ei, E);
    scan1_k<<<nb, 256>>>(N);
    scan2_k<<<1, 256>>>(nb);
    scan3_dinv_k<<<nb, 256>>>(N);
    fill_csr_k<<<(E + 255) / 256, 256>>>(E);

    // join, then full layer-0 gather (hs unscaled -> per-edge dinv weighting)
    cudaStreamWaitEvent(0, evJoin, 0);
    gather_k<<<(N + 7) / 8, 256>>>(0, 0, 0, out, 0, N);
    cudaEventRecord(evG0, 0);
    cudaStreamWaitEvent(s2, evG0, 0);

    // ---- layers 1-3: two-stream half-row pipeline ----
    // stream 0 owns rows/nodes [0, Mh); stream s2 owns [Mh, N).
    for (int layer = 1; layer < 4; layer++) {
        gemm_tc_k<<<gA, 256, GEMM_SMEM, 0 >>>(0, Mh, layer, 1);
        cudaEventRecord(evMA[layer], 0);
        gemm_tc_k<<<gB, 256, GEMM_SMEM, s2>>>(Mh, N, layer, 1);
        cudaEventRecord(evMB[layer], s2);

        int last = (layer == 3) ? 1 : 0;
        // gatherA needs both gemm halves: same-stream gemmA + cross evMB
        cudaStreamWaitEvent(0, evMB[layer], 0);
        gather_k<<<gaA, 256, 0, 0 >>>(last, layer, 1, out, 0, Mh);
        // gatherB symmetric
        cudaStreamWaitEvent(s2, evMA[layer], 0);
        gather_k<<<gaB, 256, 0, s2>>>(last, layer, 1, out, Mh, N);
        // next-layer gemmA follows gatherA on stream 0 (needs g_a[0,Mh) only);
        // next-layer gemmB follows gatherB on s2 (needs g_a[Mh,N) only).
    }

    // final join so all output writes precede stream-0 completion
    cudaEventRecord(evEnd, s2);
    cudaStreamWaitEvent(0, evEnd, 0);
    (void)n_in; (void)out_size;
}